// round 12
// baseline (speedup 1.0000x reference)
#include <cuda_runtime.h>
#include <cstdint>

#define GRIDX 128
#define NTH   512
#define BB    128
#define BBD   256            // duplicated act row stride (floats)
#define SS    512
#define II    128
#define HH    512

// ---------------- persistent device state (all acts duplicated [k][2b]) --------
static __device__ __align__(16) float g_xT[(size_t)SS*II*BBD];  // [t][i][2b]
static __device__ __align__(16) float g_h0T[2][HH*BBD];         // [u][2b]
static __device__ __align__(16) float g_h1T[2][HH*BBD];
static __device__ __align__(16) float g_decT[II*BBD];           // [i][2b]
static __device__ unsigned g_arrive = 0;
static __device__ unsigned g_release = 0;

__device__ __forceinline__ float sigf(float x){ return 1.0f/(1.0f+__expf(-x)); }
__device__ __forceinline__ float tanhf_(float x){ return 1.0f - 2.0f/(__expf(2.0f*x)+1.0f); }

typedef unsigned long long ull;
#define PACK2(d,lo,hi) asm("mov.b64 %0,{%1,%2};" : "=l"(d) : "f"(lo),"f"(hi))
#define FMA2(d,a,b)    asm("fma.rn.f32x2 %0,%1,%2,%0;" : "+l"(d) : "l"(a),"l"(b))

// software grid barrier: 128 co-resident CTAs (1 CTA/SM via ~178KB smem)
__device__ __forceinline__ void grid_sync(unsigned base, unsigned target)
{
    __syncthreads();
    if (threadIdx.x == 0) {
        __threadfence();
        unsigned arrived = atomicAdd(&g_arrive, 1u);
        if (arrived == GRIDX - 1u) {
            g_arrive = 0u;
            __threadfence();
            atomicAdd(&g_release, 1u);
        } else {
            volatile unsigned* rel = &g_release;
            while ((*rel - base) < target) { __nanosleep(32); }
        }
        __threadfence();
    }
    __syncthreads();
}

// Weights -> SMEM as Wc[k][16]; col c = unit*4+gate, global row R = gate*H+u0+unit.
__device__ void load_layer_weights(float* Wc, float* bias, int lenA,
                                   const float* __restrict__ W_ih,
                                   const float* __restrict__ W_hh,
                                   const float* __restrict__ b_ih,
                                   const float* __restrict__ b_hh, int u0)
{
    const int tid = threadIdx.x;
    const int K = lenA + HH;
    for (int idx = tid; idx < K * 16; idx += NTH) {
        int k  = idx >> 4;
        int c  = idx & 15;
        int j  = c >> 2;
        int gt = c & 3;
        int R  = gt * HH + u0 + j;
        Wc[idx] = (k < lenA) ? W_ih[R * lenA + k] : W_hh[R * HH + (k - lenA)];
    }
    if (tid < 16) {
        int j = tid >> 2, gt = tid & 3;
        int R = gt * HH + u0 + j;
        bias[tid] = b_ih[R] + b_hh[R];
    }
}

// One LSTM layer step: 16 warps = 8 k-slices x 2 col-halves.
// Warp w: ws = w>>1 owns k in [ws*K/8,(ws+1)*K/8), p = w&1 owns cols p*8..p*8+8.
// Lane l owns batches 4l..4l+3 (dup floats at 8l). acc[bp 0..3][cpair 0..3] f32x2.
__device__ void lstm_step(const float* __restrict__ srcA, int lenA,
                          const float* __restrict__ srcB,
                          const float* __restrict__ Wc, const float* __restrict__ bias_s,
                          ull* __restrict__ red,
                          float* __restrict__ hOut, float& c_st, int ub)
{
    const int tid = threadIdx.x;
    const int w = tid >> 5, l = tid & 31;
    const int ws = w >> 1, p = w & 1;
    const int K = lenA + HH;
    const int kper = K >> 3;
    const int k0 = ws * kper, k1 = k0 + kper;

    ull acc[4][4];
#pragma unroll
    for (int bp = 0; bp < 4; bp++)
#pragma unroll
        for (int cp = 0; cp < 4; cp++) { float z = 0.0f; PACK2(acc[bp][cp], z, z); }

    // per-k: W01/W23 = natural f32x2 col-pairs (no PACK); A0/A1 = dup acts
#define FMAK(A0v, A1v, KK)                                                       \
    do {                                                                         \
        const ulonglong2* wp = (const ulonglong2*)(Wc + (KK) * 16 + p * 8);      \
        ulonglong2 W01 = wp[0], W23 = wp[1];                                     \
        FMA2(acc[0][0], (A0v).x, W01.x); FMA2(acc[0][1], (A0v).x, W01.y);        \
        FMA2(acc[0][2], (A0v).x, W23.x); FMA2(acc[0][3], (A0v).x, W23.y);        \
        FMA2(acc[1][0], (A0v).y, W01.x); FMA2(acc[1][1], (A0v).y, W01.y);        \
        FMA2(acc[1][2], (A0v).y, W23.x); FMA2(acc[1][3], (A0v).y, W23.y);        \
        FMA2(acc[2][0], (A1v).x, W01.x); FMA2(acc[2][1], (A1v).x, W01.y);        \
        FMA2(acc[2][2], (A1v).x, W23.x); FMA2(acc[2][3], (A1v).x, W23.y);        \
        FMA2(acc[3][0], (A1v).y, W01.x); FMA2(acc[3][1], (A1v).y, W01.y);        \
        FMA2(acc[3][2], (A1v).y, W23.x); FMA2(acc[3][3], (A1v).y, W23.y);        \
    } while (0)

    // pipelined over groups of 2 k-rows (all segment lengths are even)
#define SEGLOOP(BASE, OFS, S0, S1)                                               \
    do {                                                                         \
        int s0 = (S0), s1 = (S1);                                                \
        if (s1 > s0) {                                                           \
            const float* bp_ = (BASE) + l * 8 - (size_t)(OFS) * BBD;             \
            ulonglong2 A[2][2], Bv[2][2];                                        \
            _Pragma("unroll")                                                    \
            for (int g = 0; g < 2; g++) {                                        \
                const ulonglong2* rp = (const ulonglong2*)(bp_ + (size_t)(s0 + g) * BBD); \
                A[g][0] = rp[0]; A[g][1] = rp[1];                                \
            }                                                                    \
            for (int gk = s0; gk < s1; gk += 2) {                                \
                if (gk + 2 < s1) {                                               \
                    _Pragma("unroll")                                            \
                    for (int g = 0; g < 2; g++) {                                \
                        const ulonglong2* rp = (const ulonglong2*)(bp_ + (size_t)(gk + 2 + g) * BBD); \
                        Bv[g][0] = rp[0]; Bv[g][1] = rp[1];                      \
                    }                                                            \
                }                                                                \
                _Pragma("unroll")                                                \
                for (int g = 0; g < 2; g++)                                      \
                    FMAK(A[g][0], A[g][1], gk + g);                              \
                if (gk + 2 < s1) {                                               \
                    _Pragma("unroll")                                            \
                    for (int g = 0; g < 2; g++) {                                \
                        A[g][0] = Bv[g][0]; A[g][1] = Bv[g][1];                  \
                    }                                                            \
                }                                                                \
            }                                                                    \
        }                                                                        \
    } while (0)

    SEGLOOP(srcA, 0, k0, (k1 < lenA ? k1 : lenA));      // segment A
    SEGLOOP(srcB, lenA, (k0 > lenA ? k0 : lenA), k1);   // segment B
#undef SEGLOOP
#undef FMAK

    // reduction store: red[(w*32+l)*17 + bp*4+cp] (padded stride kills conflicts)
    {
        ull* rp = red + (size_t)(w * 32 + l) * 17;
#pragma unroll
        for (int bp = 0; bp < 4; bp++)
#pragma unroll
            for (int cp = 0; cp < 4; cp++)
                rp[bp * 4 + cp] = acc[bp][cp];
    }
    __syncthreads();

    // gather + cell update: thread t = (ul = t>>7, b = t&127), one cell each
    const float* redf = (const float*)red;
    const int b = tid & 127;
    const int ul = tid >> 7;
    const int lane = b >> 2, bp = b & 3;
    float g4[4];
#pragma unroll
    for (int gt = 0; gt < 4; gt++) {
        const int c = ul * 4 + gt;
        const int pc = c >> 3, cp = (c & 7) >> 1, half = c & 1;
        float s = bias_s[c];
#pragma unroll
        for (int w2 = 0; w2 < 8; w2++)
            s += redf[(((size_t)((w2 * 2 + pc) * 32 + lane) * 17 + bp * 4 + cp) << 1) + half];
        g4[gt] = s;
    }
    float cn = sigf(g4[1]) * c_st + sigf(g4[0]) * tanhf_(g4[2]);
    c_st = cn;
    float h = sigf(g4[3]) * tanhf_(cn);
    *(float2*)(hOut + (size_t)(ub + ul) * BBD + 2 * b) = make_float2(h, h);
    __syncthreads();
}

// pred[b, icol] = h1[b,:] . wlin (h1 dup [u][2b]); 512 threads, 4-way split-K
__device__ void pred_step(const float* __restrict__ h1T, const float* __restrict__ wlin_s,
                          float* __restrict__ redf,
                          int t, float* __restrict__ out, int icol)
{
    const int tid = threadIdx.x;
    const int b = tid >> 2, q = tid & 3;
    const float* hp = h1T + (size_t)(q * 128) * BBD + 2 * b;
    const float* wl = wlin_s + q * 128;
    float acc = 0.0f;
#pragma unroll 8
    for (int u = 0; u < 128; u++)
        acc += hp[(size_t)u * BBD] * wl[u];
    __syncthreads();
    if (q) redf[(q - 1) * 128 + b] = acc;
    __syncthreads();
    if (!q) {
        float pr = acc + redf[b] + redf[128 + b] + redf[256 + b];
        out[((size_t)b * SS + t) * II + icol] = pr;
        *(float2*)(g_decT + (size_t)icol * BBD + 2 * b) = make_float2(pr, pr);
    }
    __syncthreads();
}

// x[b][t][i] -> xT[t][i][2b] (duplicated)
__global__ void transpose_x(const float* __restrict__ x)
{
    __shared__ float tile[32][33];
    int t = blockIdx.x;
    int i0 = blockIdx.y * 32, b0 = blockIdx.z * 32;
    int tx = threadIdx.x, ty = threadIdx.y;
#pragma unroll
    for (int j = 0; j < 32; j += 8)
        tile[ty + j][tx] = x[((size_t)(b0 + ty + j) * SS + t) * II + i0 + tx];
    __syncthreads();
#pragma unroll
    for (int j = 0; j < 32; j += 8) {
        float v = tile[tx][ty + j];
        *(float2*)(g_xT + ((size_t)t * II + i0 + ty + j) * BBD + 2 * (b0 + tx)) = make_float2(v, v);
    }
}

__global__ void __launch_bounds__(NTH, 1)
lstm_ae_kernel(const float* Wih_en0, const float* Whh_en0, const float* bih_en0, const float* bhh_en0,
               const float* Wih_en1, const float* Whh_en1, const float* bih_en1, const float* bhh_en1,
               const float* Wih_de0, const float* Whh_de0, const float* bih_de0, const float* bhh_de0,
               const float* Wih_de1, const float* Whh_de1, const float* bih_de1, const float* bhh_de1,
               const float* Wlin,
               float* __restrict__ out)
{
    extern __shared__ float sm[];
    float* Wc1    = sm;                    // 16384 f32 (K=1024 layer)
    float* Wc0    = Wc1 + 16384;           // 10240 f32 (K=640 layer)
    ull*   red    = (ull*)(Wc0 + 10240);   // 512*17 ull = 69632 B
    float* wlin_s = (float*)(red + 512 * 17); // 512
    float* bias0  = wlin_s + 512;          // 16
    float* bias1  = bias0 + 16;            // 16

    const int tid = threadIdx.x;
    const int u0  = blockIdx.x * 4;

    __shared__ unsigned s_base;
    if (tid == 0) s_base = atomicAdd(&g_release, 0u);

    // zero initial states + decoder feedback (dup arrays)
    {
        int g = blockIdx.x * NTH + tid;          // 0..65535
        for (int i = g; i < HH * BBD; i += GRIDX * NTH) { g_h0T[0][i] = 0.0f; g_h1T[0][i] = 0.0f; }
        for (int i = g; i < II * BBD; i += GRIDX * NTH) g_decT[i] = 0.0f;
    }

    load_layer_weights(Wc0, bias0, II, Wih_en0, Whh_en0, bih_en0, bhh_en0, u0);
    load_layer_weights(Wc1, bias1, HH, Wih_en1, Whh_en1, bih_en1, bhh_en1, u0);
    __syncthreads();

    unsigned base = s_base;
    unsigned nsync = 0;
    grid_sync(base, ++nsync);

    float c0 = 0.0f, c1 = 0.0f;   // one (unit,batch) cell state per thread

    int p = 0;
    // ---- encoder ----
    for (int t = 0; t < SS; t++) {
        lstm_step(g_xT + (size_t)t * II * BBD, II, g_h0T[p],
                  Wc0, bias0, red, g_h0T[p ^ 1], c0, u0);
        grid_sync(base, ++nsync);
        lstm_step(g_h0T[p ^ 1], HH, g_h1T[p],
                  Wc1, bias1, red, g_h1T[p ^ 1], c1, u0);
        grid_sync(base, ++nsync);
        p ^= 1;
    }

    // ---- swap to decoder weights ----
    load_layer_weights(Wc0, bias0, II, Wih_de0, Whh_de0, bih_de0, bhh_de0, u0);
    load_layer_weights(Wc1, bias1, HH, Wih_de1, Whh_de1, bih_de1, bhh_de1, u0);
    for (int k = tid; k < HH; k += NTH) wlin_s[k] = Wlin[blockIdx.x * HH + k];
    __syncthreads();

    // ---- decoder (closed loop) ----
    for (int t = 0; t < SS; t++) {
        lstm_step(g_decT, II, g_h0T[p],
                  Wc0, bias0, red, g_h0T[p ^ 1], c0, u0);
        grid_sync(base, ++nsync);
        lstm_step(g_h0T[p ^ 1], HH, g_h1T[p],
                  Wc1, bias1, red, g_h1T[p ^ 1], c1, u0);
        grid_sync(base, ++nsync);
        pred_step(g_h1T[p ^ 1], wlin_s, (float*)red, t, out, blockIdx.x);
        grid_sync(base, ++nsync);
        p ^= 1;
    }
}

extern "C" void kernel_launch(void* const* d_in, const int* in_sizes, int n_in,
                              void* d_out, int out_size)
{
    const float* p[18];
    for (int i = 0; i < 18; i++) p[i] = (const float*)d_in[i];

    transpose_x<<<dim3(SS, II / 32, BB / 32), dim3(32, 8)>>>(p[0]);

    const size_t shmem = (16384 + 10240) * 4 + 512 * 17 * 8 + (512 + 16 + 16) * 4; // 178304 B
    cudaFuncSetAttribute(lstm_ae_kernel, cudaFuncAttributeMaxDynamicSharedMemorySize, (int)shmem);

    lstm_ae_kernel<<<GRIDX, NTH, shmem>>>(
        p[1], p[2], p[3], p[4],
        p[5], p[6], p[7], p[8],
        p[9], p[10], p[11], p[12],
        p[13], p[14], p[15], p[16],
        p[17],
        (float*)d_out);
}

// round 13
// speedup vs baseline: 1.2775x; 1.2775x over previous
#include <cuda_runtime.h>
#include <cstdint>

#define GRIDX 128
#define NTH   256
#define BB    128
#define SS    512
#define II    128
#define HH    512

// ---------------- persistent device state (no allocations allowed) -------------
static __device__ __align__(16) float g_xT[(size_t)SS*II*BB];   // [t][i][b]
static __device__ __align__(16) float g_h0T[2][HH*BB];          // [u][b]
static __device__ __align__(16) float g_h1T[2][HH*BB];
static __device__ __align__(16) float g_decT[II*BB];            // [i][b]
static __device__ unsigned g_arrive = 0;
static __device__ unsigned g_release = 0;

__device__ __forceinline__ float sigf(float x){ return 1.0f/(1.0f+__expf(-x)); }
__device__ __forceinline__ float tanhf_(float x){ return 1.0f - 2.0f/(__expf(2.0f*x)+1.0f); }

// ---- packed f32x2 (dual-rate fp32; proven) ----
typedef unsigned long long ull;
#define PACK2(d,lo,hi) asm("mov.b64 %0,{%1,%2};" : "=l"(d) : "f"(lo),"f"(hi))
#define FMA2(d,a,b)    asm("fma.rn.f32x2 %0,%1,%2,%0;" : "+l"(d) : "l"(a),"l"(b))

// ---- cp.async (per-thread commit groups; ring staged per warp) ----
#define CPA16(d,s) asm volatile("cp.async.cg.shared.global [%0],[%1],16;" :: "r"(d),"l"(s))
#define CPC()      asm volatile("cp.async.commit_group;")
#define CPW(n)     asm volatile("cp.async.wait_group %0;" :: "n"(n))
#define SYNCWARP() asm volatile("bar.warp.sync 0xFFFFFFFF;" ::: "memory")

// software grid barrier: 128 co-resident CTAs (1 CTA/SM via ~218KB smem)
__device__ __forceinline__ void grid_sync(unsigned base, unsigned target)
{
    __syncthreads();
    if (threadIdx.x == 0) {
        __threadfence();
        unsigned arrived = atomicAdd(&g_arrive, 1u);
        if (arrived == GRIDX - 1u) {
            g_arrive = 0u;
            __threadfence();
            atomicAdd(&g_release, 1u);
        } else {
            volatile unsigned* rel = &g_release;
            while ((*rel - base) < target) { __nanosleep(32); }
        }
        __threadfence();
    }
    __syncthreads();
}

// Weights -> SMEM as Wc[k][16]; col c = unit*4+gate, global row R = gate*H+u0+unit.
__device__ void load_layer_weights(float* Wc, float* bias, int lenA,
                                   const float* __restrict__ W_ih,
                                   const float* __restrict__ W_hh,
                                   const float* __restrict__ b_ih,
                                   const float* __restrict__ b_hh, int u0)
{
    const int tid = threadIdx.x;
    const int K = lenA + HH;
    for (int idx = tid; idx < K * 16; idx += NTH) {
        int k  = idx >> 4;
        int c  = idx & 15;
        int j  = c >> 2;
        int gt = c & 3;
        int R  = gt * HH + u0 + j;
        Wc[idx] = (k < lenA) ? W_ih[R * lenA + k] : W_hh[R * HH + (k - lenA)];
    }
    if (tid < 16) {
        int j = tid >> 2, gt = tid & 3;
        int R = gt * HH + u0 + j;
        bias[tid] = b_ih[R] + b_hh[R];
    }
}

// stage one 4-row act group (4 x 512B) into SMEM ring slot via cp.async + commit
__device__ __forceinline__ void stage_group(uint32_t dst, const float* __restrict__ srcRow0, int l)
{
#pragma unroll
    for (int q = 0; q < 4; q++) {
        int idx = l + 32 * q;                 // 0..127 chunks of 16B
        int row = idx >> 5, off = (idx & 31) * 16;
        CPA16(dst + (uint32_t)(row * 512 + off),
              (const char*)(srcRow0 + (size_t)row * BB) + off);
    }
    CPC();
}

// One LSTM layer step for this CTA's 4 units over 128 batches (R11 tile).
// warp w handles k-slice [w*K/8,(w+1)*K/8); lane: bg = l>>1 (8 batches), gg = l&1 (8 cols).
// Acts staged gmem->SMEM ring (depth 3) via cp.async; consumed with LDS.
__device__ void lstm_step(const float* __restrict__ srcA, int lenA,
                          const float* __restrict__ srcB,
                          const float* __restrict__ Wc, const float* __restrict__ bias_s,
                          ull* __restrict__ red, float* __restrict__ ringw, uint32_t ringw_u32,
                          float* __restrict__ hOut, float* c_st, int ub)
{
    const int tid = threadIdx.x;
    const int w = tid >> 5, l = tid & 31;
    const int bg = l >> 1, gg = l & 1;
    const int K = lenA + HH;
    const int kper = K >> 3;
    const int k0 = w * kper, k1 = k0 + kper;

    ull acc[4][8];
#pragma unroll
    for (int bp = 0; bp < 4; bp++)
#pragma unroll
        for (int cp = 0; cp < 8; cp++) { float z = 0.0f; PACK2(acc[bp][cp], z, z); }

#define FMAK(A0v, A1v, KK)                                                       \
    do {                                                                         \
        const float4* wp = (const float4*)(Wc + (KK) * 16 + gg * 8);             \
        float4 wa = wp[0], wb = wp[1];                                           \
        ull w0,w1,w2,w3,w4,w5,w6,w7;                                             \
        PACK2(w0, wa.x, wa.x); PACK2(w1, wa.y, wa.y);                            \
        PACK2(w2, wa.z, wa.z); PACK2(w3, wa.w, wa.w);                            \
        PACK2(w4, wb.x, wb.x); PACK2(w5, wb.y, wb.y);                            \
        PACK2(w6, wb.z, wb.z); PACK2(w7, wb.w, wb.w);                            \
        FMA2(acc[0][0], (A0v).x, w0); FMA2(acc[0][1], (A0v).x, w1);              \
        FMA2(acc[0][2], (A0v).x, w2); FMA2(acc[0][3], (A0v).x, w3);              \
        FMA2(acc[0][4], (A0v).x, w4); FMA2(acc[0][5], (A0v).x, w5);              \
        FMA2(acc[0][6], (A0v).x, w6); FMA2(acc[0][7], (A0v).x, w7);              \
        FMA2(acc[1][0], (A0v).y, w0); FMA2(acc[1][1], (A0v).y, w1);              \
        FMA2(acc[1][2], (A0v).y, w2); FMA2(acc[1][3], (A0v).y, w3);              \
        FMA2(acc[1][4], (A0v).y, w4); FMA2(acc[1][5], (A0v).y, w5);              \
        FMA2(acc[1][6], (A0v).y, w6); FMA2(acc[1][7], (A0v).y, w7);              \
        FMA2(acc[2][0], (A1v).x, w0); FMA2(acc[2][1], (A1v).x, w1);              \
        FMA2(acc[2][2], (A1v).x, w2); FMA2(acc[2][3], (A1v).x, w3);              \
        FMA2(acc[2][4], (A1v).x, w4); FMA2(acc[2][5], (A1v).x, w5);              \
        FMA2(acc[2][6], (A1v).x, w6); FMA2(acc[2][7], (A1v).x, w7);              \
        FMA2(acc[3][0], (A1v).y, w0); FMA2(acc[3][1], (A1v).y, w1);              \
        FMA2(acc[3][2], (A1v).y, w2); FMA2(acc[3][3], (A1v).y, w3);              \
        FMA2(acc[3][4], (A1v).y, w4); FMA2(acc[3][5], (A1v).y, w5);              \
        FMA2(acc[3][6], (A1v).y, w6); FMA2(acc[3][7], (A1v).y, w7);              \
    } while (0)

    // cp.async-pipelined segment: k in [S0,S1), act rows at BASE + (k-OFS)*BB.
    // (S1-S0) divisible by 4 for every warp slice in this problem.
#define SEGLOOP(BASE, OFS, S0, S1)                                               \
    do {                                                                         \
        int s0 = (S0), s1 = (S1);                                                \
        if (s1 > s0) {                                                           \
            const float* bp_ = (BASE) - (size_t)(OFS) * BB;                      \
            const int ng = (s1 - s0) >> 2;                                       \
            stage_group(ringw_u32, bp_ + (size_t)s0 * BB, l);                    \
            if (ng > 1) stage_group(ringw_u32 + 2048u, bp_ + (size_t)(s0 + 4) * BB, l); \
            for (int g = 0; g < ng; g++) {                                       \
                if (g + 2 < ng) {                                                \
                    int slot = (g + 2) % 3;                                      \
                    stage_group(ringw_u32 + (uint32_t)slot * 2048u,              \
                                bp_ + (size_t)(s0 + (g + 2) * 4) * BB, l);       \
                    CPW(2);                                                      \
                } else if (g + 1 < ng) {                                         \
                    CPW(1);                                                      \
                } else {                                                         \
                    CPW(0);                                                      \
                }                                                                \
                SYNCWARP();                                                      \
                const float* sl = ringw + (size_t)(g % 3) * 512 + bg * 8;        \
                _Pragma("unroll")                                                \
                for (int r = 0; r < 4; r++) {                                    \
                    ulonglong2 Av = ((const ulonglong2*)(sl + r * 128))[0];      \
                    ulonglong2 Aw = ((const ulonglong2*)(sl + r * 128))[1];      \
                    FMAK(Av, Aw, s0 + g * 4 + r);                                \
                }                                                                \
                SYNCWARP();                                                      \
            }                                                                    \
        }                                                                        \
    } while (0)

    // segment A: k in [k0,k1) ∩ [0,lenA); segment B: k in [k0,k1) ∩ [lenA,K)
    SEGLOOP(srcA, 0, k0, (k1 < lenA ? k1 : lenA));
    SEGLOOP(srcB, lenA, (k0 > lenA ? k0 : lenA), k1);
#undef SEGLOOP
#undef FMAK

    // split-K-8 reduction through SMEM: red[w][lane][bp*8+cp] (ull)
    {
        ull* rp = red + ((size_t)(w * 32 + l) << 5);
#pragma unroll
        for (int bp = 0; bp < 4; bp++)
#pragma unroll
            for (int cp = 0; cp < 8; cp++)
                rp[bp * 8 + cp] = acc[bp][cp];
    }
    __syncthreads();

    // gather + cell update: thread t handles (b = t&127, ul = (t>>7)*2 + j), j=0,1
    const float* redf = (const float*)red;
    const int b = tid & 127;
    const int ulbase = (tid >> 7) * 2;
#pragma unroll
    for (int j = 0; j < 2; j++) {
        const int ul = ulbase + j;
        float g4[4];
#pragma unroll
        for (int gt = 0; gt < 4; gt++) {
            const int c = ul * 4 + gt;
            const int lane = (b >> 3) * 2 + (c >> 3);
            const int cp = c & 7, bp = (b & 7) >> 1, half = b & 1;
            float s = bias_s[c];
#pragma unroll
            for (int w2 = 0; w2 < 8; w2++)
                s += redf[((((w2 * 32 + lane) << 5) + bp * 8 + cp) << 1) + half];
            g4[gt] = s;
        }
        float cn = sigf(g4[1]) * c_st[j] + sigf(g4[0]) * tanhf_(g4[2]);
        c_st[j] = cn;
        hOut[(size_t)(ub + ul) * BB + b] = sigf(g4[3]) * tanhf_(cn);
    }
    __syncthreads();
}

// pred[b, icol] = h1[b,:] . wlin  (h1 stored transposed [u][b]); gmem-direct
__device__ void pred_step(const float* __restrict__ h1T, const float* __restrict__ wlin_s,
                          float* __restrict__ redf,
                          int t, float* __restrict__ out, int icol)
{
    const int tid = threadIdx.x;
    const int b = tid >> 1, half = tid & 1;
    const float* hp = h1T + (size_t)(half * 256) * BB + b;
    const float* wl = wlin_s + half * 256;
    float acc = 0.0f;
#pragma unroll 8
    for (int u = 0; u < 256; u++)
        acc += hp[(size_t)u * BB] * wl[u];
    __syncthreads();
    if (half) redf[b] = acc;
    __syncthreads();
    if (!half) {
        float p = acc + redf[b];
        out[((size_t)b * SS + t) * II + icol] = p;
        g_decT[icol * BB + b] = p;
    }
    __syncthreads();
}

// x[b][t][i] -> xT[t][i][b]
__global__ void transpose_x(const float* __restrict__ x)
{
    __shared__ float tile[32][33];
    int t = blockIdx.x;
    int i0 = blockIdx.y * 32, b0 = blockIdx.z * 32;
    int tx = threadIdx.x, ty = threadIdx.y;
#pragma unroll
    for (int j = 0; j < 32; j += 8)
        tile[ty + j][tx] = x[((size_t)(b0 + ty + j) * SS + t) * II + i0 + tx];
    __syncthreads();
#pragma unroll
    for (int j = 0; j < 32; j += 8)
        g_xT[((size_t)t * II + i0 + ty + j) * BB + b0 + tx] = tile[tx][ty + j];
}

__global__ void __launch_bounds__(NTH, 1)
lstm_ae_kernel(const float* Wih_en0, const float* Whh_en0, const float* bih_en0, const float* bhh_en0,
               const float* Wih_en1, const float* Whh_en1, const float* bih_en1, const float* bhh_en1,
               const float* Wih_de0, const float* Whh_de0, const float* bih_de0, const float* bhh_de0,
               const float* Wih_de1, const float* Whh_de1, const float* bih_de1, const float* bhh_de1,
               const float* Wlin,
               float* __restrict__ out)
{
    extern __shared__ float sm[];
    float* Wc1    = sm;                    // 16384 f32 (K=1024 layer)
    float* Wc0    = Wc1 + 16384;           // 10240 f32 (K=640 layer)
    ull*   red    = (ull*)(Wc0 + 10240);   // 8192 ull = 64KB
    float* ring   = (float*)(red + 8192);  // 8 warps * 3 slots * 512 f32 = 48KB
    float* wlin_s = ring + 12288;          // 512
    float* bias0  = wlin_s + 512;          // 16
    float* bias1  = bias0 + 16;            // 16

    const int tid = threadIdx.x;
    const int u0  = blockIdx.x * 4;
    const int w   = tid >> 5;

    float* ringw = ring + (size_t)w * 1536;
    uint32_t ringw_u32;
    {
        uint32_t b32;
        asm("{ .reg .u64 t; cvta.to.shared.u64 t, %1; cvt.u32.u64 %0, t; }" : "=r"(b32) : "l"(ringw));
        ringw_u32 = b32;
    }

    __shared__ unsigned s_base;
    if (tid == 0) s_base = atomicAdd(&g_release, 0u);

    // zero initial states + decoder feedback
    {
        int g = blockIdx.x * NTH + tid;
        for (int i = g; i < HH * BB; i += GRIDX * NTH) { g_h0T[0][i] = 0.0f; g_h1T[0][i] = 0.0f; }
        for (int i = g; i < II * BB; i += GRIDX * NTH) g_decT[i] = 0.0f;
    }

    load_layer_weights(Wc0, bias0, II, Wih_en0, Whh_en0, bih_en0, bhh_en0, u0);
    load_layer_weights(Wc1, bias1, HH, Wih_en1, Whh_en1, bih_en1, bhh_en1, u0);
    __syncthreads();

    unsigned base = s_base;
    unsigned nsync = 0;
    grid_sync(base, ++nsync);

    float c0[2] = {0.f, 0.f};
    float c1[2] = {0.f, 0.f};

    int p = 0;
    // ---- encoder ----
    for (int t = 0; t < SS; t++) {
        lstm_step(g_xT + (size_t)t * II * BB, II, g_h0T[p],
                  Wc0, bias0, red, ringw, ringw_u32, g_h0T[p ^ 1], c0, u0);
        grid_sync(base, ++nsync);
        lstm_step(g_h0T[p ^ 1], HH, g_h1T[p],
                  Wc1, bias1, red, ringw, ringw_u32, g_h1T[p ^ 1], c1, u0);
        grid_sync(base, ++nsync);
        p ^= 1;
    }

    // ---- swap to decoder weights ----
    load_layer_weights(Wc0, bias0, II, Wih_de0, Whh_de0, bih_de0, bhh_de0, u0);
    load_layer_weights(Wc1, bias1, HH, Wih_de1, Whh_de1, bih_de1, bhh_de1, u0);
    for (int k = tid; k < HH; k += NTH) wlin_s[k] = Wlin[blockIdx.x * HH + k];
    __syncthreads();

    // ---- decoder (closed loop) ----
    for (int t = 0; t < SS; t++) {
        lstm_step(g_decT, II, g_h0T[p],
                  Wc0, bias0, red, ringw, ringw_u32, g_h0T[p ^ 1], c0, u0);
        grid_sync(base, ++nsync);
        lstm_step(g_h0T[p ^ 1], HH, g_h1T[p],
                  Wc1, bias1, red, ringw, ringw_u32, g_h1T[p ^ 1], c1, u0);
        grid_sync(base, ++nsync);
        pred_step(g_h1T[p ^ 1], wlin_s, (float*)red, t, out, blockIdx.x);
        grid_sync(base, ++nsync);
        p ^= 1;
    }
}

extern "C" void kernel_launch(void* const* d_in, const int* in_sizes, int n_in,
                              void* d_out, int out_size)
{
    const float* p[18];
    for (int i = 0; i < 18; i++) p[i] = (const float*)d_in[i];

    transpose_x<<<dim3(SS, II / 32, BB / 32), dim3(32, 8)>>>(p[0]);

    // 16384+10240 f32 + 8192 ull + 12288 f32 ring + 544 f32 = 223360 B
    const size_t shmem = (16384 + 10240) * 4 + 8192 * 8 + (12288 + 512 + 16 + 16) * 4;
    cudaFuncSetAttribute(lstm_ae_kernel, cudaFuncAttributeMaxDynamicSharedMemorySize, (int)shmem);

    lstm_ae_kernel<<<GRIDX, NTH, shmem>>>(
        p[1], p[2], p[3], p[4],
        p[5], p[6], p[7], p[8],
        p[9], p[10], p[11], p[12],
        p[13], p[14], p[15], p[16],
        p[17],
        (float*)d_out);
}

// round 14
// speedup vs baseline: 1.2996x; 1.0173x over previous
#include <cuda_runtime.h>
#include <cstdint>

#define GRIDX 128
#define NTH   256
#define BB    128
#define SS    512
#define II    128
#define HH    512

// ---------------- persistent device state (no allocations allowed) -------------
static __device__ __align__(16) float g_xT[(size_t)SS*II*BB];   // [t][i][b]
static __device__ __align__(16) float g_h0T[2][HH*BB];          // [u][b]
static __device__ __align__(16) float g_h1T[2][HH*BB];
static __device__ __align__(16) float g_decT[II*BB];            // [i][b]
static __device__ unsigned g_arrive = 0;
static __device__ unsigned g_release = 0;

__device__ __forceinline__ float sigf(float x){ return 1.0f/(1.0f+__expf(-x)); }
__device__ __forceinline__ float tanhf_(float x){ return 1.0f - 2.0f/(__expf(2.0f*x)+1.0f); }

// ---- packed f32x2 (dual-rate fp32; proven) ----
typedef unsigned long long ull;
#define PACK2(d,lo,hi) asm("mov.b64 %0,{%1,%2};" : "=l"(d) : "f"(lo),"f"(hi))
#define FMA2(d,a,b)    asm("fma.rn.f32x2 %0,%1,%2,%0;" : "+l"(d) : "l"(a),"l"(b))

// ---- cp.async (per-thread commit groups; ring staged per warp) ----
#define CPA16(d,s) asm volatile("cp.async.cg.shared.global [%0],[%1],16;" :: "r"(d),"l"(s))
#define CPC()      asm volatile("cp.async.commit_group;")
#define CPW(n)     asm volatile("cp.async.wait_group %0;" :: "n"(n))
#define SYNCWARP() asm volatile("bar.warp.sync 0xFFFFFFFF;" ::: "memory")

// software grid barrier: 128 co-resident CTAs (1 CTA/SM via ~202KB smem)
__device__ __forceinline__ void grid_sync(unsigned base, unsigned target)
{
    __syncthreads();
    if (threadIdx.x == 0) {
        __threadfence();
        unsigned arrived = atomicAdd(&g_arrive, 1u);
        if (arrived == GRIDX - 1u) {
            g_arrive = 0u;
            __threadfence();
            atomicAdd(&g_release, 1u);
        } else {
            volatile unsigned* rel = &g_release;
            while ((*rel - base) < target) { __nanosleep(32); }
        }
        __threadfence();
    }
    __syncthreads();
}

// Weights -> SMEM as Wc[k][16]; col c = unit*4+gate, global row R = gate*H+u0+unit.
__device__ void load_layer_weights(float* Wc, float* bias, int lenA,
                                   const float* __restrict__ W_ih,
                                   const float* __restrict__ W_hh,
                                   const float* __restrict__ b_ih,
                                   const float* __restrict__ b_hh, int u0)
{
    const int tid = threadIdx.x;
    const int K = lenA + HH;
    for (int idx = tid; idx < K * 16; idx += NTH) {
        int k  = idx >> 4;
        int c  = idx & 15;
        int j  = c >> 2;
        int gt = c & 3;
        int R  = gt * HH + u0 + j;
        Wc[idx] = (k < lenA) ? W_ih[R * lenA + k] : W_hh[R * HH + (k - lenA)];
    }
    if (tid < 16) {
        int j = tid >> 2, gt = tid & 3;
        int R = gt * HH + u0 + j;
        bias[tid] = b_ih[R] + b_hh[R];
    }
}

// stage one 8-row act group (8 x 512B = 4KB) into SMEM ring slot via cp.async
__device__ __forceinline__ void stage_group(uint32_t dst, const float* __restrict__ srcRow0, int l)
{
#pragma unroll
    for (int q = 0; q < 8; q++) {
        int idx = l + 32 * q;                 // 0..255 chunks of 16B
        int row = idx >> 5, off = (idx & 31) * 16;
        CPA16(dst + (uint32_t)(row * 512 + off),
              (const char*)(srcRow0 + (size_t)row * BB) + off);
    }
    CPC();
}

// One LSTM layer step for this CTA's 4 units over 128 batches (R11 tile).
// warp w handles k-slice [w*K/8,(w+1)*K/8); lane: bg = l>>1 (8 batches), gg = l&1 (8 cols).
// Acts staged gmem->SMEM ring (3 slots x 8 rows) via cp.async; consumed with LDS.
__device__ void lstm_step(const float* __restrict__ srcA, int lenA,
                          const float* __restrict__ srcB,
                          const float* __restrict__ Wc, const float* __restrict__ bias_s,
                          ull* __restrict__ red, float* __restrict__ ringw, uint32_t ringw_u32,
                          float* __restrict__ hOut, float* c_st, int ub)
{
    const int tid = threadIdx.x;
    const int w = tid >> 5, l = tid & 31;
    const int bg = l >> 1, gg = l & 1;
    const int K = lenA + HH;
    const int kper = K >> 3;
    const int k0 = w * kper, k1 = k0 + kper;

    ull acc[4][8];
#pragma unroll
    for (int bp = 0; bp < 4; bp++)
#pragma unroll
        for (int cp = 0; cp < 8; cp++) { float z = 0.0f; PACK2(acc[bp][cp], z, z); }

#define FMAK(A0v, A1v, KK)                                                       \
    do {                                                                         \
        const float4* wp = (const float4*)(Wc + (KK) * 16 + gg * 8);             \
        float4 wa = wp[0], wb = wp[1];                                           \
        ull w0,w1,w2,w3,w4,w5,w6,w7;                                             \
        PACK2(w0, wa.x, wa.x); PACK2(w1, wa.y, wa.y);                            \
        PACK2(w2, wa.z, wa.z); PACK2(w3, wa.w, wa.w);                            \
        PACK2(w4, wb.x, wb.x); PACK2(w5, wb.y, wb.y);                            \
        PACK2(w6, wb.z, wb.z); PACK2(w7, wb.w, wb.w);                            \
        FMA2(acc[0][0], (A0v).x, w0); FMA2(acc[0][1], (A0v).x, w1);              \
        FMA2(acc[0][2], (A0v).x, w2); FMA2(acc[0][3], (A0v).x, w3);              \
        FMA2(acc[0][4], (A0v).x, w4); FMA2(acc[0][5], (A0v).x, w5);              \
        FMA2(acc[0][6], (A0v).x, w6); FMA2(acc[0][7], (A0v).x, w7);              \
        FMA2(acc[1][0], (A0v).y, w0); FMA2(acc[1][1], (A0v).y, w1);              \
        FMA2(acc[1][2], (A0v).y, w2); FMA2(acc[1][3], (A0v).y, w3);              \
        FMA2(acc[1][4], (A0v).y, w4); FMA2(acc[1][5], (A0v).y, w5);              \
        FMA2(acc[1][6], (A0v).y, w6); FMA2(acc[1][7], (A0v).y, w7);              \
        FMA2(acc[2][0], (A1v).x, w0); FMA2(acc[2][1], (A1v).x, w1);              \
        FMA2(acc[2][2], (A1v).x, w2); FMA2(acc[2][3], (A1v).x, w3);              \
        FMA2(acc[2][4], (A1v).x, w4); FMA2(acc[2][5], (A1v).x, w5);              \
        FMA2(acc[2][6], (A1v).x, w6); FMA2(acc[2][7], (A1v).x, w7);              \
        FMA2(acc[3][0], (A1v).y, w0); FMA2(acc[3][1], (A1v).y, w1);              \
        FMA2(acc[3][2], (A1v).y, w2); FMA2(acc[3][3], (A1v).y, w3);              \
        FMA2(acc[3][4], (A1v).y, w4); FMA2(acc[3][5], (A1v).y, w5);              \
        FMA2(acc[3][6], (A1v).y, w6); FMA2(acc[3][7], (A1v).y, w7);              \
    } while (0)

    // cp.async-pipelined segment: 8-row groups, 3-slot ring, prefetch distance 2.
    // (S1-S0) divisible by 8 for every warp slice in this problem.
#define SEGLOOP(BASE, OFS, S0, S1)                                               \
    do {                                                                         \
        int s0 = (S0), s1 = (S1);                                                \
        if (s1 > s0) {                                                           \
            const float* bp_ = (BASE) - (size_t)(OFS) * BB;                      \
            const int ng = (s1 - s0) >> 3;                                       \
            stage_group(ringw_u32, bp_ + (size_t)s0 * BB, l);                    \
            if (ng > 1) stage_group(ringw_u32 + 4096u, bp_ + (size_t)(s0 + 8) * BB, l); \
            for (int g = 0; g < ng; g++) {                                       \
                if (g + 2 < ng) {                                                \
                    int slot = (g + 2) % 3;                                      \
                    stage_group(ringw_u32 + (uint32_t)slot * 4096u,              \
                                bp_ + (size_t)(s0 + (g + 2) * 8) * BB, l);       \
                    CPW(2);                                                      \
                } else if (g + 1 < ng) {                                         \
                    CPW(1);                                                      \
                } else {                                                         \
                    CPW(0);                                                      \
                }                                                                \
                SYNCWARP();                                                      \
                const float* sl = ringw + (size_t)(g % 3) * 1024 + bg * 8;       \
                _Pragma("unroll")                                                \
                for (int r = 0; r < 8; r++) {                                    \
                    ulonglong2 Av = ((const ulonglong2*)(sl + r * 128))[0];      \
                    ulonglong2 Aw = ((const ulonglong2*)(sl + r * 128))[1];      \
                    FMAK(Av, Aw, s0 + g * 8 + r);                                \
                }                                                                \
                SYNCWARP();                                                      \
            }                                                                    \
        }                                                                        \
    } while (0)

    // segment A: k in [k0,k1) ∩ [0,lenA); segment B: k in [k0,k1) ∩ [lenA,K)
    SEGLOOP(srcA, 0, k0, (k1 < lenA ? k1 : lenA));
    SEGLOOP(srcB, lenA, (k0 > lenA ? k0 : lenA), k1);
#undef SEGLOOP
#undef FMAK

    // red ALIASES the ring: all warps must finish consuming ring data first
    __syncthreads();

    // split-K-8 reduction through SMEM: red[w][lane][bp*8+cp] (ull)
    {
        ull* rp = red + ((size_t)(w * 32 + l) << 5);
#pragma unroll
        for (int bp = 0; bp < 4; bp++)
#pragma unroll
            for (int cp = 0; cp < 8; cp++)
                rp[bp * 8 + cp] = acc[bp][cp];
    }
    __syncthreads();

    // gather + cell update: thread t handles (b = t&127, ul = (t>>7)*2 + j), j=0,1
    const float* redf = (const float*)red;
    const int b = tid & 127;
    const int ulbase = (tid >> 7) * 2;
#pragma unroll
    for (int j = 0; j < 2; j++) {
        const int ul = ulbase + j;
        float g4[4];
#pragma unroll
        for (int gt = 0; gt < 4; gt++) {
            const int c = ul * 4 + gt;
            const int lane = (b >> 3) * 2 + (c >> 3);
            const int cp = c & 7, bp = (b & 7) >> 1, half = b & 1;
            float s = bias_s[c];
#pragma unroll
            for (int w2 = 0; w2 < 8; w2++)
                s += redf[((((w2 * 32 + lane) << 5) + bp * 8 + cp) << 1) + half];
            g4[gt] = s;
        }
        float cn = sigf(g4[1]) * c_st[j] + sigf(g4[0]) * tanhf_(g4[2]);
        c_st[j] = cn;
        hOut[(size_t)(ub + ul) * BB + b] = sigf(g4[3]) * tanhf_(cn);
    }
    __syncthreads();
}

// pred[b, icol] = h1[b,:] . wlin  (h1 stored transposed [u][b]); gmem-direct
__device__ void pred_step(const float* __restrict__ h1T, const float* __restrict__ wlin_s,
                          float* __restrict__ redf,
                          int t, float* __restrict__ out, int icol)
{
    const int tid = threadIdx.x;
    const int b = tid >> 1, half = tid & 1;
    const float* hp = h1T + (size_t)(half * 256) * BB + b;
    const float* wl = wlin_s + half * 256;
    float acc = 0.0f;
#pragma unroll 8
    for (int u = 0; u < 256; u++)
        acc += hp[(size_t)u * BB] * wl[u];
    __syncthreads();
    if (half) redf[b] = acc;
    __syncthreads();
    if (!half) {
        float p = acc + redf[b];
        out[((size_t)b * SS + t) * II + icol] = p;
        g_decT[icol * BB + b] = p;
    }
    __syncthreads();
}

// x[b][t][i] -> xT[t][i][b]
__global__ void transpose_x(const float* __restrict__ x)
{
    __shared__ float tile[32][33];
    int t = blockIdx.x;
    int i0 = blockIdx.y * 32, b0 = blockIdx.z * 32;
    int tx = threadIdx.x, ty = threadIdx.y;
#pragma unroll
    for (int j = 0; j < 32; j += 8)
        tile[ty + j][tx] = x[((size_t)(b0 + ty + j) * SS + t) * II + i0 + tx];
    __syncthreads();
#pragma unroll
    for (int j = 0; j < 32; j += 8)
        g_xT[((size_t)t * II + i0 + ty + j) * BB + b0 + tx] = tile[tx][ty + j];
}

__global__ void __launch_bounds__(NTH, 1)
lstm_ae_kernel(const float* Wih_en0, const float* Whh_en0, const float* bih_en0, const float* bhh_en0,
               const float* Wih_en1, const float* Whh_en1, const float* bih_en1, const float* bhh_en1,
               const float* Wih_de0, const float* Whh_de0, const float* bih_de0, const float* bhh_de0,
               const float* Wih_de1, const float* Whh_de1, const float* bih_de1, const float* bhh_de1,
               const float* Wlin,
               float* __restrict__ out)
{
    extern __shared__ float sm[];
    float* Wc1    = sm;                    // 16384 f32 (K=1024 layer)
    float* Wc0    = Wc1 + 16384;           // 10240 f32 (K=640 layer)
    float* ring   = Wc0 + 10240;           // 8 warps * 3 slots * 1024 f32 = 96KB
    ull*   red    = (ull*)ring;            // ALIASED: reduction runs after ring drained
    float* wlin_s = ring + 24576;          // 512
    float* bias0  = wlin_s + 512;          // 16
    float* bias1  = bias0 + 16;            // 16

    const int tid = threadIdx.x;
    const int u0  = blockIdx.x * 4;
    const int w   = tid >> 5;

    float* ringw = ring + (size_t)w * 3072;
    uint32_t ringw_u32;
    {
        uint32_t b32;
        asm("{ .reg .u64 t; cvta.to.shared.u64 t, %1; cvt.u32.u64 %0, t; }" : "=r"(b32) : "l"(ringw));
        ringw_u32 = b32;
    }

    __shared__ unsigned s_base;
    if (tid == 0) s_base = atomicAdd(&g_release, 0u);

    // zero initial states + decoder feedback
    {
        int g = blockIdx.x * NTH + tid;
        for (int i = g; i < HH * BB; i += GRIDX * NTH) { g_h0T[0][i] = 0.0f; g_h1T[0][i] = 0.0f; }
        for (int i = g; i < II * BB; i += GRIDX * NTH) g_decT[i] = 0.0f;
    }

    load_layer_weights(Wc0, bias0, II, Wih_en0, Whh_en0, bih_en0, bhh_en0, u0);
    load_layer_weights(Wc1, bias1, HH, Wih_en1, Whh_en1, bih_en1, bhh_en1, u0);
    __syncthreads();

    unsigned base = s_base;
    unsigned nsync = 0;
    grid_sync(base, ++nsync);

    float c0[2] = {0.f, 0.f};
    float c1[2] = {0.f, 0.f};

    int p = 0;
    // ---- encoder ----
    for (int t = 0; t < SS; t++) {
        lstm_step(g_xT + (size_t)t * II * BB, II, g_h0T[p],
                  Wc0, bias0, red, ringw, ringw_u32, g_h0T[p ^ 1], c0, u0);
        grid_sync(base, ++nsync);
        lstm_step(g_h0T[p ^ 1], HH, g_h1T[p],
                  Wc1, bias1, red, ringw, ringw_u32, g_h1T[p ^ 1], c1, u0);
        grid_sync(base, ++nsync);
        p ^= 1;
    }

    // ---- swap to decoder weights ----
    load_layer_weights(Wc0, bias0, II, Wih_de0, Whh_de0, bih_de0, bhh_de0, u0);
    load_layer_weights(Wc1, bias1, HH, Wih_de1, Whh_de1, bih_de1, bhh_de1, u0);
    for (int k = tid; k < HH; k += NTH) wlin_s[k] = Wlin[blockIdx.x * HH + k];
    __syncthreads();

    // ---- decoder (closed loop) ----
    for (int t = 0; t < SS; t++) {
        lstm_step(g_decT, II, g_h0T[p],
                  Wc0, bias0, red, ringw, ringw_u32, g_h0T[p ^ 1], c0, u0);
        grid_sync(base, ++nsync);
        lstm_step(g_h0T[p ^ 1], HH, g_h1T[p],
                  Wc1, bias1, red, ringw, ringw_u32, g_h1T[p ^ 1], c1, u0);
        grid_sync(base, ++nsync);
        pred_step(g_h1T[p ^ 1], wlin_s, (float*)red, t, out, blockIdx.x);
        grid_sync(base, ++nsync);
        p ^= 1;
    }
}

extern "C" void kernel_launch(void* const* d_in, const int* in_sizes, int n_in,
                              void* d_out, int out_size)
{
    const float* p[18];
    for (int i = 0; i < 18; i++) p[i] = (const float*)d_in[i];

    transpose_x<<<dim3(SS, II / 32, BB / 32), dim3(32, 8)>>>(p[0]);

    // 16384 + 10240 + 24576 + 512 + 16 + 16 = 51744 f32 = 206976 B
    const size_t shmem = (16384 + 10240 + 24576 + 512 + 16 + 16) * sizeof(float);
    cudaFuncSetAttribute(lstm_ae_kernel, cudaFuncAttributeMaxDynamicSharedMemorySize, (int)shmem);

    lstm_ae_kernel<<<GRIDX, NTH, shmem>>>(
        p[1], p[2], p[3], p[4],
        p[5], p[6], p[7], p[8],
        p[9], p[10], p[11], p[12],
        p[13], p[14], p[15], p[16],
        p[17],
        (float*)d_out);
}

// round 15
// speedup vs baseline: 1.5162x; 1.1666x over previous
#include <cuda_runtime.h>
#include <cstdint>

#define GRIDX 128
#define NTH   512
#define BB    128
#define SS    512
#define II    128
#define HH    512

// ---------------- persistent device state (no allocations allowed) -------------
static __device__ __align__(16) float g_xT[(size_t)SS*II*BB];   // [t][i][b]
static __device__ __align__(16) float g_h0T[2][HH*BB];          // [u][b]
static __device__ __align__(16) float g_h1T[2][HH*BB];
static __device__ __align__(16) float g_decT[II*BB];            // [i][b]
static __device__ unsigned g_arrive = 0;
static __device__ unsigned g_release = 0;

__device__ __forceinline__ float sigf(float x){ return 1.0f/(1.0f+__expf(-x)); }
__device__ __forceinline__ float tanhf_(float x){ return 1.0f - 2.0f/(__expf(2.0f*x)+1.0f); }

// ---- packed f32x2 (dual-rate fp32; proven) ----
typedef unsigned long long ull;
#define PACK2(d,lo,hi) asm("mov.b64 %0,{%1,%2};" : "=l"(d) : "f"(lo),"f"(hi))
#define FMA2(d,a,b)    asm("fma.rn.f32x2 %0,%1,%2,%0;" : "+l"(d) : "l"(a),"l"(b))

// ---- cp.async (per-thread commit groups; PRIVATE ring per warp) ----
#define CPA16(d,s) asm volatile("cp.async.cg.shared.global [%0],[%1],16;" :: "r"(d),"l"(s))
#define CPC()      asm volatile("cp.async.commit_group;")
#define CPW(n)     asm volatile("cp.async.wait_group %0;" :: "n"(n))
#define SYNCWARP() asm volatile("bar.warp.sync 0xFFFFFFFF;" ::: "memory")

// software grid barrier: 128 co-resident CTAs (1 CTA/SM via ~222KB smem)
__device__ __forceinline__ void grid_sync(unsigned base, unsigned target)
{
    __syncthreads();
    if (threadIdx.x == 0) {
        __threadfence();
        unsigned arrived = atomicAdd(&g_arrive, 1u);
        if (arrived == GRIDX - 1u) {
            g_arrive = 0u;
            __threadfence();
            atomicAdd(&g_release, 1u);
        } else {
            volatile unsigned* rel = &g_release;
            while ((*rel - base) < target) { __nanosleep(32); }
        }
        __threadfence();
    }
    __syncthreads();
}

// Weights -> SMEM as Wc[k][16]; col c = unit*4+gate, global row R = gate*H+u0+unit.
__device__ void load_layer_weights(float* Wc, float* bias, int lenA,
                                   const float* __restrict__ W_ih,
                                   const float* __restrict__ W_hh,
                                   const float* __restrict__ b_ih,
                                   const float* __restrict__ b_hh, int u0)
{
    const int tid = threadIdx.x;
    const int K = lenA + HH;
    for (int idx = tid; idx < K * 16; idx += NTH) {
        int k  = idx >> 4;
        int c  = idx & 15;
        int j  = c >> 2;
        int gt = c & 3;
        int R  = gt * HH + u0 + j;
        Wc[idx] = (k < lenA) ? W_ih[R * lenA + k] : W_hh[R * HH + (k - lenA)];
    }
    if (tid < 16) {
        int j = tid >> 2, gt = tid & 3;
        int R = gt * HH + u0 + j;
        bias[tid] = b_ih[R] + b_hh[R];
    }
}

// stage one 4-row x 256B act half-panel into private ring slot (2 CPA16/thread)
__device__ __forceinline__ void stage_group(uint32_t dst, const float* __restrict__ srcRow0,
                                            int l, int bhOff)
{
#pragma unroll
    for (int q = 0; q < 2; q++) {
        int idx = l + 32 * q;                 // 0..63 chunks of 16B
        int row = idx >> 4, off = (idx & 15) * 16;
        CPA16(dst + (uint32_t)(row * 256 + off),
              (const char*)(srcRow0 + (size_t)row * BB + bhOff) + off);
    }
    CPC();
}

// One LSTM layer step: 16 warps = 8 k-slices x 2 batch-halves.
// Warp w: ws = w&7 owns k in [ws*K/8,(ws+1)*K/8), bh = w>>3 owns batches bh*64..+64.
// Lane l: bq = l>>1 (2 batch-pairs), gg = l&1 (8 cols). acc[2][8] f32x2 (batch pairs).
__device__ void lstm_step(const float* __restrict__ srcA, int lenA,
                          const float* __restrict__ srcB,
                          const float* __restrict__ Wc, const float* __restrict__ bias_s,
                          ull* __restrict__ red, float* __restrict__ ringw, uint32_t ringw_u32,
                          float* __restrict__ hOut, float& c_st, int ub)
{
    const int tid = threadIdx.x;
    const int w = tid >> 5, l = tid & 31;
    const int ws = w & 7, bh = w >> 3;
    const int bq = l >> 1, gg = l & 1;
    const int bhOff = bh * 64;                 // float offset into each 128-b row
    const int K = lenA + HH;
    const int kper = K >> 3;
    const int k0 = ws * kper, k1 = k0 + kper;

    ull acc[2][8];
#pragma unroll
    for (int j = 0; j < 2; j++)
#pragma unroll
        for (int cp = 0; cp < 8; cp++) { float z = 0.0f; PACK2(acc[j][cp], z, z); }

#define FMAK(Av, KK)                                                             \
    do {                                                                         \
        const float4* wp = (const float4*)(Wc + (KK) * 16 + gg * 8);             \
        float4 wa = wp[0], wb = wp[1];                                           \
        ull w0,w1,w2,w3,w4,w5,w6,w7;                                             \
        PACK2(w0, wa.x, wa.x); PACK2(w1, wa.y, wa.y);                            \
        PACK2(w2, wa.z, wa.z); PACK2(w3, wa.w, wa.w);                            \
        PACK2(w4, wb.x, wb.x); PACK2(w5, wb.y, wb.y);                            \
        PACK2(w6, wb.z, wb.z); PACK2(w7, wb.w, wb.w);                            \
        FMA2(acc[0][0], (Av).x, w0); FMA2(acc[0][1], (Av).x, w1);                \
        FMA2(acc[0][2], (Av).x, w2); FMA2(acc[0][3], (Av).x, w3);                \
        FMA2(acc[0][4], (Av).x, w4); FMA2(acc[0][5], (Av).x, w5);                \
        FMA2(acc[0][6], (Av).x, w6); FMA2(acc[0][7], (Av).x, w7);                \
        FMA2(acc[1][0], (Av).y, w0); FMA2(acc[1][1], (Av).y, w1);                \
        FMA2(acc[1][2], (Av).y, w2); FMA2(acc[1][3], (Av).y, w3);                \
        FMA2(acc[1][4], (Av).y, w4); FMA2(acc[1][5], (Av).y, w5);                \
        FMA2(acc[1][6], (Av).y, w6); FMA2(acc[1][7], (Av).y, w7);                \
    } while (0)

    // cp.async-pipelined segment: 4-row groups, private 3-slot ring, prefetch 2.
    // (S1-S0) divisible by 4 for every warp slice in this problem.
#define SEGLOOP(BASE, OFS, S0, S1)                                               \
    do {                                                                         \
        int s0 = (S0), s1 = (S1);                                                \
        if (s1 > s0) {                                                           \
            const float* bp_ = (BASE) - (size_t)(OFS) * BB;                      \
            const int ng = (s1 - s0) >> 2;                                       \
            stage_group(ringw_u32, bp_ + (size_t)s0 * BB, l, bhOff);             \
            if (ng > 1) stage_group(ringw_u32 + 1024u, bp_ + (size_t)(s0 + 4) * BB, l, bhOff); \
            for (int g = 0; g < ng; g++) {                                       \
                if (g + 2 < ng) {                                                \
                    int slot = (g + 2) % 3;                                      \
                    stage_group(ringw_u32 + (uint32_t)slot * 1024u,              \
                                bp_ + (size_t)(s0 + (g + 2) * 4) * BB, l, bhOff);\
                    CPW(2);                                                      \
                } else if (g + 1 < ng) {                                         \
                    CPW(1);                                                      \
                } else {                                                         \
                    CPW(0);                                                      \
                }                                                                \
                SYNCWARP();                                                      \
                const float* sl = ringw + (size_t)(g % 3) * 256 + bq * 4;        \
                _Pragma("unroll")                                                \
                for (int r = 0; r < 4; r++) {                                    \
                    ulonglong2 Av = ((const ulonglong2*)(sl + r * 64))[0];       \
                    FMAK(Av, s0 + g * 4 + r);                                    \
                }                                                                \
                SYNCWARP();                                                      \
            }                                                                    \
        }                                                                        \
    } while (0)

    // segment A: k in [k0,k1) ∩ [0,lenA); segment B: k in [k0,k1) ∩ [lenA,K)
    SEGLOOP(srcA, 0, k0, (k1 < lenA ? k1 : lenA));
    SEGLOOP(srcB, lenA, (k0 > lenA ? k0 : lenA), k1);
#undef SEGLOOP
#undef FMAK

    // split-K-8 reduction (per batch-half): red[(w*32+l)*17 + j*8+cp] (ull, padded)
    {
        ull* rp = red + (size_t)(w * 32 + l) * 17;
#pragma unroll
        for (int j = 0; j < 2; j++)
#pragma unroll
            for (int cp = 0; cp < 8; cp++)
                rp[j * 8 + cp] = acc[j][cp];
    }
    __syncthreads();

    // gather + cell update: thread t = (ul = t>>7, b = t&127), one cell each
    const float* redf = (const float*)red;
    const int b = tid & 127;
    const int ul = tid >> 7;
    const int bhg = b >> 6, bb = b & 63;
    const int bqg = bb >> 2, jg = (bb >> 1) & 1, half = bb & 1;
    float g4[4];
#pragma unroll
    for (int gt = 0; gt < 4; gt++) {
        const int c = ul * 4 + gt;
        const int ggc = c >> 3, cp = c & 7;
        const int lane = bqg * 2 + ggc;
        float s = bias_s[c];
#pragma unroll
        for (int ws2 = 0; ws2 < 8; ws2++) {
            int w2 = bhg * 8 + ws2;
            s += redf[(((size_t)(w2 * 32 + lane) * 17 + jg * 8 + cp) << 1) + half];
        }
        g4[gt] = s;
    }
    float cn = sigf(g4[1]) * c_st + sigf(g4[0]) * tanhf_(g4[2]);
    c_st = cn;
    hOut[(size_t)(ub + ul) * BB + b] = sigf(g4[3]) * tanhf_(cn);
    __syncthreads();
}

// pred[b, icol] = h1[b,:] . wlin (h1 transposed [u][b]); 512 threads, 4-way split-K
__device__ void pred_step(const float* __restrict__ h1T, const float* __restrict__ wlin_s,
                          float* __restrict__ redf,
                          int t, float* __restrict__ out, int icol)
{
    const int tid = threadIdx.x;
    const int b = tid >> 2, q = tid & 3;
    const float* hp = h1T + (size_t)(q * 128) * BB + b;
    const float* wl = wlin_s + q * 128;
    float acc = 0.0f;
#pragma unroll 8
    for (int u = 0; u < 128; u++)
        acc += hp[(size_t)u * BB] * wl[u];
    __syncthreads();
    if (q) redf[(q - 1) * 128 + b] = acc;
    __syncthreads();
    if (!q) {
        float pr = acc + redf[b] + redf[128 + b] + redf[256 + b];
        out[((size_t)b * SS + t) * II + icol] = pr;
        g_decT[icol * BB + b] = pr;
    }
    __syncthreads();
}

// x[b][t][i] -> xT[t][i][b]
__global__ void transpose_x(const float* __restrict__ x)
{
    __shared__ float tile[32][33];
    int t = blockIdx.x;
    int i0 = blockIdx.y * 32, b0 = blockIdx.z * 32;
    int tx = threadIdx.x, ty = threadIdx.y;
#pragma unroll
    for (int j = 0; j < 32; j += 8)
        tile[ty + j][tx] = x[((size_t)(b0 + ty + j) * SS + t) * II + i0 + tx];
    __syncthreads();
#pragma unroll
    for (int j = 0; j < 32; j += 8)
        g_xT[((size_t)t * II + i0 + ty + j) * BB + b0 + tx] = tile[tx][ty + j];
}

__global__ void __launch_bounds__(NTH, 1)
lstm_ae_kernel(const float* Wih_en0, const float* Whh_en0, const float* bih_en0, const float* bhh_en0,
               const float* Wih_en1, const float* Whh_en1, const float* bih_en1, const float* bhh_en1,
               const float* Wih_de0, const float* Whh_de0, const float* bih_de0, const float* bhh_de0,
               const float* Wih_de1, const float* Whh_de1, const float* bih_de1, const float* bhh_de1,
               const float* Wlin,
               float* __restrict__ out)
{
    extern __shared__ float sm[];
    float* Wc1    = sm;                        // 16384 f32 (K=1024 layer)
    float* Wc0    = Wc1 + 16384;               // 10240 f32 (K=640 layer)
    ull*   red    = (ull*)(Wc0 + 10240);       // 512*17 ull = 69632 B
    float* ring   = (float*)(red + 512 * 17);  // 16 warps * 3 slots * 256 f32 = 48KB
    float* wlin_s = ring + 12288;              // 512
    float* bias0  = wlin_s + 512;              // 16
    float* bias1  = bias0 + 16;                // 16

    const int tid = threadIdx.x;
    const int u0  = blockIdx.x * 4;
    const int w   = tid >> 5;

    float* ringw = ring + (size_t)w * 768;     // private 3 x 256-f32 slots
    uint32_t ringw_u32;
    {
        uint32_t b32;
        asm("{ .reg .u64 t; cvta.to.shared.u64 t, %1; cvt.u32.u64 %0, t; }" : "=r"(b32) : "l"(ringw));
        ringw_u32 = b32;
    }

    __shared__ unsigned s_base;
    if (tid == 0) s_base = atomicAdd(&g_release, 0u);

    // zero initial states + decoder feedback
    {
        int g = blockIdx.x * NTH + tid;        // 0..65535
        g_h0T[0][g] = 0.0f; g_h1T[0][g] = 0.0f;
        if (g < II * BB) g_decT[g] = 0.0f;
    }

    load_layer_weights(Wc0, bias0, II, Wih_en0, Whh_en0, bih_en0, bhh_en0, u0);
    load_layer_weights(Wc1, bias1, HH, Wih_en1, Whh_en1, bih_en1, bhh_en1, u0);
    __syncthreads();

    unsigned base = s_base;
    unsigned nsync = 0;
    grid_sync(base, ++nsync);

    float c0 = 0.0f, c1 = 0.0f;   // one (unit,batch) cell state per thread

    int p = 0;
    // ---- encoder ----
    for (int t = 0; t < SS; t++) {
        lstm_step(g_xT + (size_t)t * II * BB, II, g_h0T[p],
                  Wc0, bias0, red, ringw, ringw_u32, g_h0T[p ^ 1], c0, u0);
        grid_sync(base, ++nsync);
        lstm_step(g_h0T[p ^ 1], HH, g_h1T[p],
                  Wc1, bias1, red, ringw, ringw_u32, g_h1T[p ^ 1], c1, u0);
        grid_sync(base, ++nsync);
        p ^= 1;
    }

    // ---- swap to decoder weights ----
    load_layer_weights(Wc0, bias0, II, Wih_de0, Whh_de0, bih_de0, bhh_de0, u0);
    load_layer_weights(Wc1, bias1, HH, Wih_de1, Whh_de1, bih_de1, bhh_de1, u0);
    for (int k = tid; k < HH; k += NTH) wlin_s[k] = Wlin[blockIdx.x * HH + k];
    __syncthreads();

    // ---- decoder (closed loop) ----
    for (int t = 0; t < SS; t++) {
        lstm_step(g_decT, II, g_h0T[p],
                  Wc0, bias0, red, ringw, ringw_u32, g_h0T[p ^ 1], c0, u0);
        grid_sync(base, ++nsync);
        lstm_step(g_h0T[p ^ 1], HH, g_h1T[p],
                  Wc1, bias1, red, ringw, ringw_u32, g_h1T[p ^ 1], c1, u0);
        grid_sync(base, ++nsync);
        pred_step(g_h1T[p ^ 1], wlin_s, (float*)red, t, out, blockIdx.x);
        grid_sync(base, ++nsync);
        p ^= 1;
    }
}

extern "C" void kernel_launch(void* const* d_in, const int* in_sizes, int n_in,
                              void* d_out, int out_size)
{
    const float* p[18];
    for (int i = 0; i < 18; i++) p[i] = (const float*)d_in[i];

    transpose_x<<<dim3(SS, II / 32, BB / 32), dim3(32, 8)>>>(p[0]);

    // 106496 + 69632 + 49152 + 2048 + 128 = 227456 B
    const size_t shmem = (16384 + 10240) * 4 + 512 * 17 * 8 + (12288 + 512 + 16 + 16) * 4;
    cudaFuncSetAttribute(lstm_ae_kernel, cudaFuncAttributeMaxDynamicSharedMemorySize, (int)shmem);

    lstm_ae_kernel<<<GRIDX, NTH, shmem>>>(
        p[1], p[2], p[3], p[4],
        p[5], p[6], p[7], p[8],
        p[9], p[10], p[11], p[12],
        p[13], p[14], p[15], p[16],
        p[17],
        (float*)d_out);
}